// round 7
// baseline (speedup 1.0000x reference)
#include <cuda_runtime.h>
#include <math.h>

#define C_   256
#define H_   50
#define W_   50
#define R_   128
#define PH_  7
#define PW_  7
#define NBIN 49
#define BH_  10
#define BW_  10
#define SS_  0.0625f
#define SI_  1.0f
#define SO_  1.8f

// f32 RN reciprocal of 7, folded at compile time (0x3E124925) — matches
// XLA/LLVM's fast-math "divide by constant -> multiply by reciprocal".
#define RCP7 (1.0f / 7.0f)

__device__ float g_ft[H_ * W_ * C_];   // ft[(h*W + w)*C + c]

struct Geo {
    int hs, he, ws, we;
    int hs_in, he_in, ws_in, we_in;
    float bsh, bsw;
};

__device__ __forceinline__ int rnd_f(float v) {
    return (int)floorf(__fadd_rn(__fmul_rn(v, SS_), 0.5f));
}

__device__ __forceinline__ Geo compute_geo(const float* __restrict__ rois, int r) {
    const float x1 = rois[r * 5 + 1];
    const float y1 = rois[r * 5 + 2];
    const float x2 = rois[r * 5 + 3];
    const float y2 = rois[r * 5 + 4];
    const float cx = __fmul_rn(__fadd_rn(x1, x2), 0.5f);
    const float cy = __fmul_rn(__fadd_rn(y1, y2), 0.5f);
    const float wh = __fmul_rn(__fsub_rn(x2, x1), 0.5f);
    const float hh = __fmul_rn(__fsub_rn(y2, y1), 0.5f);

    Geo g;
    g.hs    = rnd_f(__fsub_rn(cy, __fmul_rn(hh, SO_)));
    g.he    = rnd_f(__fadd_rn(cy, __fmul_rn(hh, SO_)));
    g.ws    = rnd_f(__fsub_rn(cx, __fmul_rn(wh, SO_)));
    g.we    = rnd_f(__fadd_rn(cx, __fmul_rn(wh, SO_)));
    g.hs_in = rnd_f(__fsub_rn(cy, __fmul_rn(hh, SI_)));
    g.he_in = rnd_f(__fadd_rn(cy, __fmul_rn(hh, SI_)));
    g.ws_in = rnd_f(__fsub_rn(cx, __fmul_rn(wh, SI_)));
    g.we_in = rnd_f(__fadd_rn(cx, __fmul_rn(wh, SI_)));

    const float roi_h = (float)max(g.he - g.hs + 1, 1);
    const float roi_w = (float)max(g.we - g.ws + 1, 1);
    // KEY CHANGE (under test): reciprocal multiply, NOT division.
    g.bsh = __fmul_rn(roi_h, RCP7);
    g.bsw = __fmul_rn(roi_w, RCP7);
    return g;
}

__device__ __forceinline__ void bin_bounds(const Geo& g, int ph, int pw,
                                           int& hstart, int& hend,
                                           int& wstart, int& wend) {
    hstart = (int)floorf(__fmul_rn((float)ph,       g.bsh)) + g.hs;
    hend   = (int)ceilf (__fmul_rn((float)(ph + 1), g.bsh)) + g.hs;
    wstart = (int)floorf(__fmul_rn((float)pw,       g.bsw)) + g.ws;
    wend   = (int)ceilf (__fmul_rn((float)(pw + 1), g.bsw)) + g.ws;
    hstart = min(max(hstart, 0), H_);
    hend   = min(max(hend,   0), H_);
    wstart = min(max(wstart, 0), W_);
    wend   = min(max(wend,   0), W_);
}

// ---------------------------------------------------------------------------
__global__ void transpose_kernel(const float* __restrict__ f) {
    __shared__ float tile[32][33];
    const int P = H_ * W_;
    int p0 = blockIdx.x * 32;
    int c0 = blockIdx.y * 32;
    int tx = threadIdx.x, ty = threadIdx.y;

    #pragma unroll
    for (int j = 0; j < 32; j += 8) {
        int p = p0 + tx, c = c0 + ty + j;
        tile[ty + j][tx] = (p < P) ? f[c * P + p] : 0.0f;
    }
    __syncthreads();
    #pragma unroll
    for (int j = 0; j < 32; j += 8) {
        int p = p0 + ty + j, c = c0 + tx;
        if (p < P) g_ft[p * C_ + c] = tile[tx][ty + j];
    }
}

// ---------------------------------------------------------------------------
// Pool: strict ring, +0.5 rounding, reciprocal-multiply bin scale.
// ---------------------------------------------------------------------------
__global__ __launch_bounds__(256) void pool_kernel(const float* __restrict__ rois,
                                                   float* __restrict__ out) {
    const int r    = blockIdx.x >> 3;
    const int cg   = blockIdx.x & 7;
    const int lane = threadIdx.x & 31;
    const int warp = threadIdx.x >> 5;
    const int c    = cg * 32 + lane;

    __shared__ float tile[32 * NBIN];

    const Geo g = compute_geo(rois, r);

    for (int bin = warp; bin < NBIN; bin += 8) {
        const int ph = bin / PW_;
        const int pw = bin % PW_;
        int hstart, hend, wstart, wend;
        bin_bounds(g, ph, pw, hstart, hend, wstart, wend);

        const int hlim = min(hend, hstart + BH_);
        const int wlim = min(wend, wstart + BW_);

        float m = -INFINITY;
        bool found = false;
        for (int h = hstart; h < hlim; ++h) {
            const bool ih = (h > g.hs_in) && (h < g.he_in);
            const float* row = g_ft + (h * W_) * C_ + c;
            for (int w = wstart; w < wlim; ++w) {
                const bool iw = (w > g.ws_in) && (w < g.we_in);
                if (ih && iw) continue;
                float v = __ldg(row + w * C_);
                m = fmaxf(m, v);
                found = true;
            }
        }
        tile[lane * NBIN + bin] = found ? m : 0.0f;
    }
    __syncthreads();

    float* outp = out + (size_t)(r * C_ + cg * 32) * NBIN;
    for (int i = threadIdx.x; i < 32 * NBIN; i += 256)
        outp[i] = tile[i];
}

// ---------------------------------------------------------------------------
extern "C" void kernel_launch(void* const* d_in, const int* in_sizes, int n_in,
                              void* d_out, int out_size) {
    const float* features = (const float*)d_in[0];
    const float* rois     = (const float*)d_in[1];
    if (n_in >= 2 && in_sizes[0] == R_ * 5 && in_sizes[1] == C_ * H_ * W_) {
        const float* t = features; features = rois; rois = t;
    }
    float* out = (float*)d_out;

    dim3 tb(32, 8);
    dim3 tg((H_ * W_ + 31) / 32, C_ / 32);
    transpose_kernel<<<tg, tb>>>(features);
    pool_kernel<<<R_ * (C_ / 32), 256>>>(rois, out);
}

// round 8
// speedup vs baseline: 1.3756x; 1.3756x over previous
#include <cuda_runtime.h>
#include <math.h>

#define C_    256
#define H_    50
#define W_    50
#define R_    128
#define PH_   7
#define PW_   7
#define NBIN  49
#define BH_   10
#define BW_   10
#define SS_   0.0625f
#define SI_   1.0f
#define SO_   1.8f
#define SLOTS 40            // max positions per bin is 36; padded

// f32 RN reciprocal of 7 (XLA divide-by-constant fold) — bit-exact vs reference.
#define RCP7 (1.0f / 7.0f)

__device__ float g_ft[H_ * W_ * C_];            // transposed features [(h*W+w)*C + c]
__device__ int   g_pos[R_ * NBIN * SLOTS];      // pre-scaled offsets (h*W+w)*C
__device__ int   g_cnt[R_ * NBIN];

struct Geo {
    int hs, he, ws, we;
    int hs_in, he_in, ws_in, we_in;
    float bsh, bsw;
};

__device__ __forceinline__ int rnd_f(float v) {
    return (int)floorf(__fadd_rn(__fmul_rn(v, SS_), 0.5f));
}

__device__ __forceinline__ Geo compute_geo(const float* __restrict__ rois, int r) {
    const float x1 = rois[r * 5 + 1];
    const float y1 = rois[r * 5 + 2];
    const float x2 = rois[r * 5 + 3];
    const float y2 = rois[r * 5 + 4];
    const float cx = __fmul_rn(__fadd_rn(x1, x2), 0.5f);
    const float cy = __fmul_rn(__fadd_rn(y1, y2), 0.5f);
    const float wh = __fmul_rn(__fsub_rn(x2, x1), 0.5f);
    const float hh = __fmul_rn(__fsub_rn(y2, y1), 0.5f);

    Geo g;
    g.hs    = rnd_f(__fsub_rn(cy, __fmul_rn(hh, SO_)));
    g.he    = rnd_f(__fadd_rn(cy, __fmul_rn(hh, SO_)));
    g.ws    = rnd_f(__fsub_rn(cx, __fmul_rn(wh, SO_)));
    g.we    = rnd_f(__fadd_rn(cx, __fmul_rn(wh, SO_)));
    g.hs_in = rnd_f(__fsub_rn(cy, __fmul_rn(hh, SI_)));
    g.he_in = rnd_f(__fadd_rn(cy, __fmul_rn(hh, SI_)));
    g.ws_in = rnd_f(__fsub_rn(cx, __fmul_rn(wh, SI_)));
    g.we_in = rnd_f(__fadd_rn(cx, __fmul_rn(wh, SI_)));

    const float roi_h = (float)max(g.he - g.hs + 1, 1);
    const float roi_w = (float)max(g.we - g.ws + 1, 1);
    g.bsh = __fmul_rn(roi_h, RCP7);      // reciprocal multiply (bit-exact vs XLA)
    g.bsw = __fmul_rn(roi_w, RCP7);
    return g;
}

// ---------------------------------------------------------------------------
// Kernel 1: transpose (C, H*W) -> (H*W, C)
// ---------------------------------------------------------------------------
__global__ void transpose_kernel(const float* __restrict__ f) {
    __shared__ float tile[32][33];
    const int P = H_ * W_;
    int p0 = blockIdx.x * 32;
    int c0 = blockIdx.y * 32;
    int tx = threadIdx.x, ty = threadIdx.y;

    #pragma unroll
    for (int j = 0; j < 32; j += 8) {
        int p = p0 + tx, c = c0 + ty + j;
        tile[ty + j][tx] = (p < P) ? f[c * P + p] : 0.0f;
    }
    __syncthreads();
    #pragma unroll
    for (int j = 0; j < 32; j += 8) {
        int p = p0 + ty + j, c = c0 + tx;
        if (p < P) g_ft[p * C_ + c] = tile[tx][ty + j];
    }
}

// ---------------------------------------------------------------------------
// Kernel 2: per-(roi,bin) geometry -> position lists (identical semantics).
// grid = 128 (roi), block = 64 threads (thread = bin).
// ---------------------------------------------------------------------------
__global__ __launch_bounds__(64) void setup_kernel(const float* __restrict__ rois) {
    const int r   = blockIdx.x;
    const int bin = threadIdx.x;
    if (bin >= NBIN) return;

    const Geo g = compute_geo(rois, r);
    const int ph = bin / PW_;
    const int pw = bin % PW_;

    int hstart = (int)floorf(__fmul_rn((float)ph,       g.bsh)) + g.hs;
    int hend   = (int)ceilf (__fmul_rn((float)(ph + 1), g.bsh)) + g.hs;
    int wstart = (int)floorf(__fmul_rn((float)pw,       g.bsw)) + g.ws;
    int wend   = (int)ceilf (__fmul_rn((float)(pw + 1), g.bsw)) + g.ws;
    hstart = min(max(hstart, 0), H_);
    hend   = min(max(hend,   0), H_);
    wstart = min(max(wstart, 0), W_);
    wend   = min(max(wend,   0), W_);

    const int hlim = min(hend, hstart + BH_);
    const int wlim = min(wend, wstart + BW_);

    int* dst = g_pos + (r * NBIN + bin) * SLOTS;
    int k = 0;
    for (int h = hstart; h < hlim; ++h) {
        const bool ih = (h > g.hs_in) && (h < g.he_in);
        for (int w = wstart; w < wlim; ++w) {
            const bool iw = (w > g.ws_in) && (w < g.we_in);
            if (ih && iw) continue;           // ring hole
            dst[k++] = (h * W_ + w) * C_;     // pre-scaled offset
        }
    }
    g_cnt[r * NBIN + bin] = k;
}

// ---------------------------------------------------------------------------
// Kernel 3: hot pooling — pure gather + max over precomputed lists.
// grid = R*8 (roi, channel-group), block = 256.
// ---------------------------------------------------------------------------
__global__ __launch_bounds__(256) void pool_kernel(float* __restrict__ out) {
    const int r    = blockIdx.x >> 3;
    const int cg   = blockIdx.x & 7;
    const int lane = threadIdx.x & 31;
    const int warp = threadIdx.x >> 5;
    const int c    = cg * 32 + lane;
    const int tid  = threadIdx.x;

    __shared__ int   cnt_s[NBIN];
    __shared__ int   pos_s[NBIN * SLOTS];
    __shared__ float tile[32 * NBIN];

    // Stage this roi's lists into smem (coalesced).
    if (tid < NBIN) cnt_s[tid] = g_cnt[r * NBIN + tid];
    const int* src = g_pos + r * NBIN * SLOTS;
    #pragma unroll
    for (int i = tid; i < NBIN * SLOTS; i += 256) pos_s[i] = src[i];
    __syncthreads();

    const float* ftc = g_ft + c;

    for (int bin = warp; bin < NBIN; bin += 8) {
        const int cnt = cnt_s[bin];
        const int* pp = pos_s + bin * SLOTS;

        float m0 = -INFINITY, m1 = -INFINITY, m2 = -INFINITY, m3 = -INFINITY;
        int i = 0;
        for (; i + 4 <= cnt; i += 4) {
            float v0 = __ldg(ftc + pp[i + 0]);
            float v1 = __ldg(ftc + pp[i + 1]);
            float v2 = __ldg(ftc + pp[i + 2]);
            float v3 = __ldg(ftc + pp[i + 3]);
            m0 = fmaxf(m0, v0);
            m1 = fmaxf(m1, v1);
            m2 = fmaxf(m2, v2);
            m3 = fmaxf(m3, v3);
        }
        for (; i < cnt; ++i)
            m0 = fmaxf(m0, __ldg(ftc + pp[i]));

        float m = fmaxf(fmaxf(m0, m1), fmaxf(m2, m3));
        tile[lane * NBIN + bin] = (cnt > 0) ? m : 0.0f;
    }
    __syncthreads();

    float* outp = out + (size_t)(r * C_ + cg * 32) * NBIN;
    for (int i = tid; i < 32 * NBIN; i += 256)
        outp[i] = tile[i];
}

// ---------------------------------------------------------------------------
extern "C" void kernel_launch(void* const* d_in, const int* in_sizes, int n_in,
                              void* d_out, int out_size) {
    const float* features = (const float*)d_in[0];
    const float* rois     = (const float*)d_in[1];
    if (n_in >= 2 && in_sizes[0] == R_ * 5 && in_sizes[1] == C_ * H_ * W_) {
        const float* t = features; features = rois; rois = t;
    }
    float* out = (float*)d_out;

    dim3 tb(32, 8);
    dim3 tg((H_ * W_ + 31) / 32, C_ / 32);
    transpose_kernel<<<tg, tb>>>(features);
    setup_kernel<<<R_, 64>>>(rois);
    pool_kernel<<<R_ * (C_ / 32), 256>>>(out);
}

// round 9
// speedup vs baseline: 1.5779x; 1.1471x over previous
#include <cuda_runtime.h>
#include <math.h>

#define C_    256
#define H_    50
#define W_    50
#define R_    128
#define PH_   7
#define PW_   7
#define NBIN  49
#define BH_   10
#define BW_   10
#define SS_   0.0625f
#define SI_   1.0f
#define SO_   1.8f
#define SLOTS 40

// f32 RN reciprocal of 7 (XLA divide-by-constant fold) — bit-exact vs reference.
#define RCP7 (1.0f / 7.0f)

__device__ float g_ft[H_ * W_ * C_];   // transposed features [(h*W+w)*C + c]

struct Geo {
    int hs, he, ws, we;
    int hs_in, he_in, ws_in, we_in;
    float bsh, bsw;
};

__device__ __forceinline__ int rnd_f(float v) {
    return (int)floorf(__fadd_rn(__fmul_rn(v, SS_), 0.5f));
}

__device__ __forceinline__ Geo compute_geo(const float* __restrict__ rois, int r) {
    const float x1 = rois[r * 5 + 1];
    const float y1 = rois[r * 5 + 2];
    const float x2 = rois[r * 5 + 3];
    const float y2 = rois[r * 5 + 4];
    const float cx = __fmul_rn(__fadd_rn(x1, x2), 0.5f);
    const float cy = __fmul_rn(__fadd_rn(y1, y2), 0.5f);
    const float wh = __fmul_rn(__fsub_rn(x2, x1), 0.5f);
    const float hh = __fmul_rn(__fsub_rn(y2, y1), 0.5f);

    Geo g;
    g.hs    = rnd_f(__fsub_rn(cy, __fmul_rn(hh, SO_)));
    g.he    = rnd_f(__fadd_rn(cy, __fmul_rn(hh, SO_)));
    g.ws    = rnd_f(__fsub_rn(cx, __fmul_rn(wh, SO_)));
    g.we    = rnd_f(__fadd_rn(cx, __fmul_rn(wh, SO_)));
    g.hs_in = rnd_f(__fsub_rn(cy, __fmul_rn(hh, SI_)));
    g.he_in = rnd_f(__fadd_rn(cy, __fmul_rn(hh, SI_)));
    g.ws_in = rnd_f(__fsub_rn(cx, __fmul_rn(wh, SI_)));
    g.we_in = rnd_f(__fadd_rn(cx, __fmul_rn(wh, SI_)));

    const float roi_h = (float)max(g.he - g.hs + 1, 1);
    const float roi_w = (float)max(g.we - g.ws + 1, 1);
    g.bsh = __fmul_rn(roi_h, RCP7);
    g.bsw = __fmul_rn(roi_w, RCP7);
    return g;
}

// ---------------------------------------------------------------------------
// Kernel 1: transpose (C, H*W) -> (H*W, C)  [unchanged, proven]
// ---------------------------------------------------------------------------
__global__ void transpose_kernel(const float* __restrict__ f) {
    __shared__ float tile[32][33];
    const int P = H_ * W_;
    int p0 = blockIdx.x * 32;
    int c0 = blockIdx.y * 32;
    int tx = threadIdx.x, ty = threadIdx.y;

    #pragma unroll
    for (int j = 0; j < 32; j += 8) {
        int p = p0 + tx, c = c0 + ty + j;
        tile[ty + j][tx] = (p < P) ? f[c * P + p] : 0.0f;
    }
    __syncthreads();
    #pragma unroll
    for (int j = 0; j < 32; j += 8) {
        int p = p0 + ty + j, c = c0 + tx;
        if (p < P) g_ft[p * C_ + c] = tile[tx][ty + j];
    }
}

// ---------------------------------------------------------------------------
// Kernel 2: pooling. grid = R*2 (roi, 128-channel half), block = 256.
//   Prologue: threads 0..48 build this roi's position lists in smem.
//   Main: warp = bin stripe, lane = 4 channels via one LDG.128.
// ---------------------------------------------------------------------------
__global__ __launch_bounds__(256) void pool_kernel(const float* __restrict__ rois,
                                                   float* __restrict__ out) {
    const int r    = blockIdx.x >> 1;
    const int half = blockIdx.x & 1;          // which 128 channels
    const int tid  = threadIdx.x;
    const int lane = tid & 31;
    const int warp = tid >> 5;

    __shared__ int   cnt_s[NBIN];
    __shared__ int   pos_s[NBIN * SLOTS];
    __shared__ float tile[128 * NBIN];        // [c_local][bin]

    // ---- prologue: build position lists (bit-exact geometry) ----
    if (tid < NBIN) {
        const Geo g = compute_geo(rois, r);
        const int ph = tid / PW_;
        const int pw = tid % PW_;

        int hstart = (int)floorf(__fmul_rn((float)ph,       g.bsh)) + g.hs;
        int hend   = (int)ceilf (__fmul_rn((float)(ph + 1), g.bsh)) + g.hs;
        int wstart = (int)floorf(__fmul_rn((float)pw,       g.bsw)) + g.ws;
        int wend   = (int)ceilf (__fmul_rn((float)(pw + 1), g.bsw)) + g.ws;
        hstart = min(max(hstart, 0), H_);
        hend   = min(max(hend,   0), H_);
        wstart = min(max(wstart, 0), W_);
        wend   = min(max(wend,   0), W_);

        const int hlim = min(hend, hstart + BH_);
        const int wlim = min(wend, wstart + BW_);

        int* dst = pos_s + tid * SLOTS;
        int k = 0;
        for (int h = hstart; h < hlim; ++h) {
            const bool ih = (h > g.hs_in) && (h < g.he_in);
            for (int w = wstart; w < wlim; ++w) {
                const bool iw = (w > g.ws_in) && (w < g.we_in);
                if (ih && iw) continue;
                dst[k++] = (h * W_ + w) * C_;
            }
        }
        cnt_s[tid] = k;
    }
    __syncthreads();

    // ---- main: gather + max, 4 channels per lane via float4 ----
    const int c0 = half * 128 + lane * 4;
    const float* ftc = g_ft + c0;

    for (int bin = warp; bin < NBIN; bin += 8) {
        const int cnt = cnt_s[bin];
        const int* pp = pos_s + bin * SLOTS;

        float4 m0 = make_float4(-INFINITY, -INFINITY, -INFINITY, -INFINITY);
        float4 m1 = m0;
        int i = 0;
        for (; i + 2 <= cnt; i += 2) {
            const float4 v0 = __ldg((const float4*)(ftc + pp[i + 0]));
            const float4 v1 = __ldg((const float4*)(ftc + pp[i + 1]));
            m0.x = fmaxf(m0.x, v0.x); m0.y = fmaxf(m0.y, v0.y);
            m0.z = fmaxf(m0.z, v0.z); m0.w = fmaxf(m0.w, v0.w);
            m1.x = fmaxf(m1.x, v1.x); m1.y = fmaxf(m1.y, v1.y);
            m1.z = fmaxf(m1.z, v1.z); m1.w = fmaxf(m1.w, v1.w);
        }
        if (i < cnt) {
            const float4 v0 = __ldg((const float4*)(ftc + pp[i]));
            m0.x = fmaxf(m0.x, v0.x); m0.y = fmaxf(m0.y, v0.y);
            m0.z = fmaxf(m0.z, v0.z); m0.w = fmaxf(m0.w, v0.w);
        }
        m0.x = fmaxf(m0.x, m1.x); m0.y = fmaxf(m0.y, m1.y);
        m0.z = fmaxf(m0.z, m1.z); m0.w = fmaxf(m0.w, m1.w);

        const int cl = lane * 4;
        if (cnt > 0) {
            tile[(cl + 0) * NBIN + bin] = m0.x;
            tile[(cl + 1) * NBIN + bin] = m0.y;
            tile[(cl + 2) * NBIN + bin] = m0.z;
            tile[(cl + 3) * NBIN + bin] = m0.w;
        } else {
            tile[(cl + 0) * NBIN + bin] = 0.0f;
            tile[(cl + 1) * NBIN + bin] = 0.0f;
            tile[(cl + 2) * NBIN + bin] = 0.0f;
            tile[(cl + 3) * NBIN + bin] = 0.0f;
        }
    }
    __syncthreads();

    // ---- coalesced contiguous store of 128 channels x 49 bins ----
    float* outp = out + (size_t)(r * C_ + half * 128) * NBIN;
    #pragma unroll 4
    for (int i = tid; i < 128 * NBIN; i += 256)
        outp[i] = tile[i];
}

// ---------------------------------------------------------------------------
extern "C" void kernel_launch(void* const* d_in, const int* in_sizes, int n_in,
                              void* d_out, int out_size) {
    const float* features = (const float*)d_in[0];
    const float* rois     = (const float*)d_in[1];
    if (n_in >= 2 && in_sizes[0] == R_ * 5 && in_sizes[1] == C_ * H_ * W_) {
        const float* t = features; features = rois; rois = t;
    }
    float* out = (float*)d_out;

    dim3 tb(32, 8);
    dim3 tg((H_ * W_ + 31) / 32, C_ / 32);
    transpose_kernel<<<tg, tb>>>(features);
    pool_kernel<<<R_ * 2, 256>>>(rois, out);
}

// round 13
// speedup vs baseline: 1.9363x; 1.2272x over previous
#include <cuda_runtime.h>
#include <math.h>

#define C_    256
#define H_    50
#define W_    50
#define R_    128
#define PH_   7
#define PW_   7
#define NBIN  49
#define BH_   10
#define BW_   10
#define SS_   0.0625f
#define SI_   1.0f
#define SO_   1.8f
#define SLOTS 40

// f32 RN reciprocal of 7 (XLA divide-by-constant fold) — bit-exact vs reference.
#define RCP7 (1.0f / 7.0f)

__device__ float g_ft[H_ * W_ * C_];   // transposed features [(h*W+w)*C + c]

struct Geo {
    int hs, he, ws, we;
    int hs_in, he_in, ws_in, we_in;
    float bsh, bsw;
};

__device__ __forceinline__ int rnd_f(float v) {
    return (int)floorf(__fadd_rn(__fmul_rn(v, SS_), 0.5f));
}

__device__ __forceinline__ Geo compute_geo(const float* __restrict__ rois, int r) {
    const float x1 = rois[r * 5 + 1];
    const float y1 = rois[r * 5 + 2];
    const float x2 = rois[r * 5 + 3];
    const float y2 = rois[r * 5 + 4];
    const float cx = __fmul_rn(__fadd_rn(x1, x2), 0.5f);
    const float cy = __fmul_rn(__fadd_rn(y1, y2), 0.5f);
    const float wh = __fmul_rn(__fsub_rn(x2, x1), 0.5f);
    const float hh = __fmul_rn(__fsub_rn(y2, y1), 0.5f);

    Geo g;
    g.hs    = rnd_f(__fsub_rn(cy, __fmul_rn(hh, SO_)));
    g.he    = rnd_f(__fadd_rn(cy, __fmul_rn(hh, SO_)));
    g.ws    = rnd_f(__fsub_rn(cx, __fmul_rn(wh, SO_)));
    g.we    = rnd_f(__fadd_rn(cx, __fmul_rn(wh, SO_)));
    g.hs_in = rnd_f(__fsub_rn(cy, __fmul_rn(hh, SI_)));
    g.he_in = rnd_f(__fadd_rn(cy, __fmul_rn(hh, SI_)));
    g.ws_in = rnd_f(__fsub_rn(cx, __fmul_rn(wh, SI_)));
    g.we_in = rnd_f(__fadd_rn(cx, __fmul_rn(wh, SI_)));

    const float roi_h = (float)max(g.he - g.hs + 1, 1);
    const float roi_w = (float)max(g.we - g.ws + 1, 1);
    g.bsh = __fmul_rn(roi_h, RCP7);
    g.bsw = __fmul_rn(roi_w, RCP7);
    return g;
}

// ---------------------------------------------------------------------------
// Kernel 1: transpose (C, H*W) -> (H*W, C), fully vectorized:
// 1x LDG.128 + 4x STS + 4x LDS + 1x STG.128 per thread.
// ---------------------------------------------------------------------------
__global__ __launch_bounds__(256) void transpose_kernel(const float* __restrict__ f) {
    __shared__ float tile[32][33];
    const int P = H_ * W_;                 // 2500
    const int p0 = blockIdx.x * 32;
    const int c0 = blockIdx.y * 32;
    const int tid = threadIdx.x;

    // Load: thread -> (c_l = tid/8, p4 = tid%8), float4 along p.
    {
        const int c_l = tid >> 3;
        const int p4  = (tid & 7) * 4;
        const int p   = p0 + p4;
        const float* src = f + (c0 + c_l) * P + p;
        if (p + 3 < P) {
            const float4 v = __ldg((const float4*)src);
            tile[c_l][p4 + 0] = v.x;
            tile[c_l][p4 + 1] = v.y;
            tile[c_l][p4 + 2] = v.z;
            tile[c_l][p4 + 3] = v.w;
        } else {
            #pragma unroll
            for (int k = 0; k < 4; ++k)
                tile[c_l][p4 + k] = (p + k < P) ? __ldg(src + k) : 0.0f;
        }
    }
    __syncthreads();

    // Store: thread -> (p_l = tid/8, c4 = tid%8), float4 along c.
    {
        const int p_l = tid >> 3;
        const int c4  = (tid & 7) * 4;
        const int p   = p0 + p_l;
        if (p < P) {
            float4 v;
            v.x = tile[c4 + 0][p_l];
            v.y = tile[c4 + 1][p_l];
            v.z = tile[c4 + 2][p_l];
            v.w = tile[c4 + 3][p_l];
            *(float4*)(g_ft + p * C_ + c0 + c4) = v;
        }
    }
}

// ---------------------------------------------------------------------------
// Kernel 2: pooling. grid = R*7 (roi, ph-row), block = 224 (7 warps).
//   warp = bin (pw), lanes = 128 channels via float4, x2 halves.
//   Per-warp ballot-compacted position lists (order-free under max).
// ---------------------------------------------------------------------------
__global__ __launch_bounds__(224) void pool_kernel(const float* __restrict__ rois,
                                                   float* __restrict__ out) {
    const int r    = blockIdx.x / 7;
    const int ph   = blockIdx.x % 7;
    const int tid  = threadIdx.x;
    const int lane = tid & 31;
    const int warp = tid >> 5;            // = pw

    __shared__ int   pos_s[PW_ * SLOTS];
    __shared__ float tile[PW_ * 260];     // [pw][c], pad 260 for bank spread

    const Geo g = compute_geo(rois, r);   // redundant per thread; cheap

    // ---- per-warp bin bounds (bit-exact) ----
    int hstart = (int)floorf(__fmul_rn((float)ph,         g.bsh)) + g.hs;
    int hend   = (int)ceilf (__fmul_rn((float)(ph + 1),   g.bsh)) + g.hs;
    int wstart = (int)floorf(__fmul_rn((float)warp,       g.bsw)) + g.ws;
    int wend   = (int)ceilf (__fmul_rn((float)(warp + 1), g.bsw)) + g.ws;
    hstart = min(max(hstart, 0), H_);
    hend   = min(max(hend,   0), H_);
    wstart = min(max(wstart, 0), W_);
    wend   = min(max(wend,   0), W_);

    const int hspan = max(min(hend, hstart + BH_) - hstart, 0);
    const int wspan = max(min(wend, wstart + BW_) - wstart, 0);
    const int cells = hspan * wspan;

    // ---- ballot-compacted position list (this warp's smem region) ----
    int* dst = pos_s + warp * SLOTS;
    int cnt = 0;
    for (int base = 0; base < cells; base += 32) {
        const int cell = base + lane;
        bool valid = false;
        int  off = 0;
        if (cell < cells) {
            const int h = hstart + cell / wspan;
            const int w = wstart + cell % wspan;
            const bool ih = (h > g.hs_in) && (h < g.he_in);
            const bool iw = (w > g.ws_in) && (w < g.we_in);
            valid = !(ih && iw);
            off = (h * W_ + w) * C_;
        }
        const unsigned mask = __ballot_sync(0xffffffffu, valid);
        if (valid)
            dst[cnt + __popc(mask & ((1u << lane) - 1u))] = off;
        cnt += __popc(mask);
    }

    // ---- gather + max: lane covers channels [4*lane, 4*lane+3] and +128 ----
    const int cl = lane * 4;
    const float* f0 = g_ft + cl;
    const float* f1 = g_ft + cl + 128;

    float4 a = make_float4(-INFINITY, -INFINITY, -INFINITY, -INFINITY);
    float4 b = a;
    for (int i = 0; i < cnt; ++i) {
        const int p = dst[i];
        const float4 v0 = __ldg((const float4*)(f0 + p));
        const float4 v1 = __ldg((const float4*)(f1 + p));
        a.x = fmaxf(a.x, v0.x); a.y = fmaxf(a.y, v0.y);
        a.z = fmaxf(a.z, v0.z); a.w = fmaxf(a.w, v0.w);
        b.x = fmaxf(b.x, v1.x); b.y = fmaxf(b.y, v1.y);
        b.z = fmaxf(b.z, v1.z); b.w = fmaxf(b.w, v1.w);
    }
    if (cnt == 0) {
        a = make_float4(0.f, 0.f, 0.f, 0.f);
        b = a;
    }

    // ---- stage to smem: [pw][c], conflict-free STS.128 ----
    float* trow = tile + warp * 260;
    *(float4*)(trow + cl)       = a;
    *(float4*)(trow + cl + 128) = b;
    __syncthreads();

    // ---- store: out[r][c][ph*7 + pw] for all c, 7 bins of this ph row ----
    float* outp = out + (size_t)r * C_ * NBIN + ph * PW_;
    for (int j = tid; j < C_ * PW_; j += 224) {
        const int c = j / PW_;
        const int m = j % PW_;
        outp[c * NBIN + m] = tile[m * 260 + c];
    }
}

// ---------------------------------------------------------------------------
extern "C" void kernel_launch(void* const* d_in, const int* in_sizes, int n_in,
                              void* d_out, int out_size) {
    const float* features = (const float*)d_in[0];
    const float* rois     = (const float*)d_in[1];
    if (n_in >= 2 && in_sizes[0] == R_ * 5 && in_sizes[1] == C_ * H_ * W_) {
        const float* t = features; features = rois; rois = t;
    }
    float* out = (float*)d_out;

    dim3 tg((H_ * W_ + 31) / 32, C_ / 32);   // (79, 8)
    transpose_kernel<<<tg, 256>>>(features);
    pool_kernel<<<R_ * 7, 224>>>(rois, out);
}